// round 16
// baseline (speedup 1.0000x reference)
#include <cuda_runtime.h>
#include <cuda_fp16.h>
#include <math.h>

#define N_NODES 10000
#define K_NBR   32
#define C_DIM   64
#define H_DIM   64
#define ALPHA   0.3f

typedef unsigned long long u64;

// Intermediates (static device arrays -> L2-resident):
// g_H[n][l] = fp16x2 of leaky(embs[n] @ Q_w + Q_b)     1.28 MB
// g_P[n][h] = embs[n] @ W_top + W_b  (fp32)            2.56 MB
__device__ __half2 g_H[N_NODES * 32];
__device__ float   g_P[N_NODES * H_DIM];

__device__ __forceinline__ u64 pack2(float x) {
    u64 r; asm("mov.b64 %0, {%1, %1};" : "=l"(r) : "f"(x)); return r;
}
__device__ __forceinline__ u64 packf2(float2 v) {
    u64 r; asm("mov.b64 %0, {%1, %2};" : "=l"(r) : "f"(v.x), "f"(v.y)); return r;
}
__device__ __forceinline__ void ffma2(u64& d, u64 a, u64 b) {
    asm("fma.rn.f32x2 %0, %1, %2, %0;" : "+l"(d) : "l"(a), "l"(b));
}
__device__ __forceinline__ void addf2(u64& d, u64 a) {
    asm("add.rn.f32x2 %0, %0, %1;" : "+l"(d) : "l"(a));
}
__device__ __forceinline__ float2 unpack2(u64 v) {
    float2 f; asm("mov.b64 {%0, %1}, %2;" : "=f"(f.x), "=f"(f.y) : "l"(v)); return f;
}
__device__ __forceinline__ u64 h2_to_f2(unsigned int h) {
    __half2 hv = *reinterpret_cast<__half2*>(&h);
    return packf2(__half22float2(hv));
}
__device__ __forceinline__ float leaky(float x) { return x >= 0.f ? x : ALPHA * x; }

// ---------------------------------------------------------------------------
// Kernel A: per node, two 64x64 GEMVs over embs:
//   g_H = fp16(leaky(embs @ Q_w + Q_b)),  g_P = embs @ W_w[0:64] + W_b
// block = 256 (8 warps), 2 nodes/warp, grid = 625 (exact).
// Triggers programmatic launch completion EARLY so agg's preamble overlaps.
// ---------------------------------------------------------------------------
__global__ __launch_bounds__(256) void qproj_kernel(const float* __restrict__ embs,
                                                    const float* __restrict__ Qw,
                                                    const float* __restrict__ Qb,
                                                    const float* __restrict__ Ww,
                                                    const float* __restrict__ Wb) {
    __shared__ float2 sQ[C_DIM * 32];   // (Qw[c][2l], Qw[c][2l+1])
    __shared__ float2 sP[C_DIM * 32];   // W_top rows 0..63 of Ww
    __shared__ float  sE[8][2][C_DIM];

    const int tid  = threadIdx.x;
    const int lane = tid & 31;
    const int warp = tid >> 5;

    // Let the dependent agg grid launch now: its preamble (random weights
    // issue + sV fill) reads only harness inputs, not g_H/g_P.
    cudaTriggerProgrammaticLaunchCompletion();

    const float2* Q2 = (const float2*)Qw;
    const float2* W2 = (const float2*)Ww;
    for (int i = tid; i < C_DIM * 32; i += 256) { sQ[i] = Q2[i]; sP[i] = W2[i]; }
    __syncthreads();

    const int n0 = blockIdx.x * 16 + warp * 2;   // exact: 625*16 = 10000
#pragma unroll
    for (int i = 0; i < 2; ++i) {
        float2 e = ((const float2*)embs)[(n0 + i) * 32 + lane];
        *(float2*)&sE[warp][i][2 * lane] = e;
    }
    __syncwarp();

    const u64 qb = ((const u64*)Qb)[lane];
    const u64 wb = ((const u64*)Wb)[lane];
    u64 aq[2] = {qb, qb}, ap[2] = {wb, wb};

    const u64* sQ64 = (const u64*)sQ;
    const u64* sP64 = (const u64*)sP;
#pragma unroll
    for (int c = 0; c < C_DIM; c += 4) {
        u64 q0 = sQ64[(c + 0) * 32 + lane], p0 = sP64[(c + 0) * 32 + lane];
        u64 q1 = sQ64[(c + 1) * 32 + lane], p1 = sP64[(c + 1) * 32 + lane];
        u64 q2 = sQ64[(c + 2) * 32 + lane], p2 = sP64[(c + 2) * 32 + lane];
        u64 q3 = sQ64[(c + 3) * 32 + lane], p3 = sP64[(c + 3) * 32 + lane];
#pragma unroll
        for (int i = 0; i < 2; ++i) {
            float4 x = *(const float4*)&sE[warp][i][c];
            u64 x0 = pack2(x.x), x1 = pack2(x.y), x2 = pack2(x.z), x3 = pack2(x.w);
            ffma2(aq[i], x0, q0); ffma2(ap[i], x0, p0);
            ffma2(aq[i], x1, q1); ffma2(ap[i], x1, p1);
            ffma2(aq[i], x2, q2); ffma2(ap[i], x2, p2);
            ffma2(aq[i], x3, q3); ffma2(ap[i], x3, p3);
        }
    }

#pragma unroll
    for (int i = 0; i < 2; ++i) {
        float2 h = unpack2(aq[i]);
        h.x = leaky(h.x); h.y = leaky(h.y);
        g_H[(n0 + i) * 32 + lane] = __float22half2_rn(h);
        ((float2*)g_P)[(n0 + i) * 32 + lane] = unpack2(ap[i]);
    }
}

// ---------------------------------------------------------------------------
// Kernel B (fused, decoupled latencies, PDL): 1 node/warp, block 256, grid 1250.
// Preamble (nbr load, random DRAM weight issue, sV fill) runs BEFORE
// cudaGridDependencySynchronize() -> overlaps with qproj's execution.
// After the grid sync: LDG.128 gather into registers (depends only on nbr),
// weight reduce via SHFL, butterfly, then the 64x64 GEMM from sV.
// ---------------------------------------------------------------------------
__global__ __launch_bounds__(256, 4) void agg_kernel(const float* __restrict__ weights,
                                                     const int*   __restrict__ nbr,
                                                     const float* __restrict__ Ww,
                                                     float* __restrict__ out) {
    __shared__ float2 sV[H_DIM * 32];   // W_bot rows 64..127 (16 KB)
    __shared__ float  sX[8][H_DIM];     // per-warp weighted-sum-hidden vector

    const int tid  = threadIdx.x;
    const int lane = tid & 31;
    const int warp = tid >> 5;

    const int n = blockIdx.x * 8 + warp;   // exact: 1250*8 = 10000

    // ---- preamble: overlaps qproj ----
    const int   j = nbr[n * K_NBR + lane];
    const float w = __ldcs(&weights[(size_t)n * N_NODES + j]);   // random DRAM, in flight

    const uint4* W4  = (const uint4*)(Ww + 64 * H_DIM);   // W_bot rows 64..127
    uint4*       sV4 = (uint4*)sV;
#pragma unroll
    for (int i = 0; i < 4; ++i) sV4[tid + i * 256] = W4[tid + i * 256];

    // ---- wait for qproj's g_H / g_P to be complete ----
    cudaGridDependencySynchronize();

    // ---- issue ALL gather loads (depend only on j) + g_P row ----
    const int g = lane >> 3;     // group 0..3 -> neighbor k = 4t+g
    const int p = lane & 7;      // 16B chunk -> cols 8p..8p+7 of the 128B row
    const uint4* H4 = (const uint4*)g_H;   // one row = 8 uint4

    uint4 rows[8];
#pragma unroll
    for (int t = 0; t < 8; ++t) {
        int jk = __shfl_sync(0xffffffffu, j, 4 * t + g);
        rows[t] = H4[jk * 8 + p];
    }
    u64 o = ((const u64*)g_P)[n * 32 + lane];
    __syncthreads();                               // sV ready

    // ---- consume random weight: reduce + prescale ----
    float ws = w;
#pragma unroll
    for (int off = 16; off; off >>= 1) ws += __shfl_xor_sync(0xffffffffu, ws, off);
    const float wp_own = w * (1.f / (ws + 1e-6f));

    // ---- weighted accumulate of the in-register rows ----
    u64 acc[4] = {0, 0, 0, 0};
#pragma unroll
    for (int t = 0; t < 8; ++t) {
        float wk = __shfl_sync(0xffffffffu, wp_own, 4 * t + g);
        u64 wp = pack2(wk);
        ffma2(acc[0], wp, h2_to_f2(rows[t].x));
        ffma2(acc[1], wp, h2_to_f2(rows[t].y));
        ffma2(acc[2], wp, h2_to_f2(rows[t].z));
        ffma2(acc[3], wp, h2_to_f2(rows[t].w));
    }

    // butterfly-reduce partial column sums across the 4 groups (lanes ^8, ^16)
#pragma unroll
    for (int d = 0; d < 4; ++d) {
        addf2(acc[d], __shfl_xor_sync(0xffffffffu, acc[d], 8));
        addf2(acc[d], __shfl_xor_sync(0xffffffffu, acc[d], 16));
    }
    if (g == 0) {   // lanes 0..7 hold complete sums for cols 8p..8p+7
#pragma unroll
        for (int d = 0; d < 4; ++d)
            *(float2*)&sX[warp][8 * p + 2 * d] = unpack2(acc[d]);
    }
    __syncwarp();

    // ---- o += wsh @ W_bot ----
    const u64* sV64 = (const u64*)sV;
#pragma unroll
    for (int c = 0; c < H_DIM; c += 4) {
        float4 x = *(const float4*)&sX[warp][c];
        ffma2(o, pack2(x.x), sV64[(c + 0) * 32 + lane]);
        ffma2(o, pack2(x.y), sV64[(c + 1) * 32 + lane]);
        ffma2(o, pack2(x.z), sV64[(c + 2) * 32 + lane]);
        ffma2(o, pack2(x.w), sV64[(c + 3) * 32 + lane]);
    }

    // ---- leaky + L2-normalize + store ----
    float2 f = unpack2(o);
    f.x = leaky(f.x); f.y = leaky(f.y);
    float ss = f.x * f.x + f.y * f.y;
#pragma unroll
    for (int off = 16; off; off >>= 1) ss += __shfl_xor_sync(0xffffffffu, ss, off);
    const float d = 1.f / (sqrtf(ss) + 1e-6f);
    ((float2*)out)[n * 32 + lane] = make_float2(f.x * d, f.y * d);
}

// ---------------------------------------------------------------------------
// Inputs (metadata order):
//   0 embs (1,10000,64) f32   1 weights (10000,10000) f32
//   2 neighbor_set (10000,32) i32   3 Q_w (64,64) f32   4 Q_b (64,) f32
//   5 W_w (128,64) f32   6 W_b (64,) f32
// ---------------------------------------------------------------------------
extern "C" void kernel_launch(void* const* d_in, const int* in_sizes, int n_in,
                              void* d_out, int out_size) {
    const float* embs    = (const float*)d_in[0];
    const float* weights = (const float*)d_in[1];
    const int*   nbr     = (const int*)  d_in[2];
    const float* Qw      = (const float*)d_in[3];
    const float* Qb      = (const float*)d_in[4];
    const float* Ww      = (const float*)d_in[5];
    const float* Wb      = (const float*)d_in[6];
    float* out = (float*)d_out;

    qproj_kernel<<<625, 256>>>(embs, Qw, Qb, Ww, Wb);

    // PDL launch: agg starts while qproj runs; agg's grid-sync enforces the
    // g_H/g_P dependency. Falls back to normal serialization if unsupported.
    cudaLaunchConfig_t cfg = {};
    cfg.gridDim  = dim3(1250);
    cfg.blockDim = dim3(256);
    cfg.stream   = 0;
    cudaLaunchAttribute attr[1];
    attr[0].id = cudaLaunchAttributeProgrammaticStreamSerialization;
    attr[0].val.programmaticStreamSerializationAllowed = 1;
    cfg.attrs    = attr;
    cfg.numAttrs = 1;
    cudaLaunchKernelEx(&cfg, agg_kernel, weights, nbr, Ww, out);
}

// round 17
// speedup vs baseline: 1.2637x; 1.2637x over previous
#include <cuda_runtime.h>
#include <cuda_fp16.h>
#include <math.h>

#define N_NODES 10000
#define K_NBR   32
#define C_DIM   64
#define H_DIM   64
#define ALPHA   0.3f

typedef unsigned long long u64;

// Intermediates (static device arrays -> L2-resident):
// g_H[n][l] = fp16x2 of leaky(embs[n] @ Q_w + Q_b)     1.28 MB
// g_P[n][h] = embs[n] @ W_top + W_b  (fp32)            2.56 MB
__device__ __half2 g_H[N_NODES * 32];
__device__ float   g_P[N_NODES * H_DIM];

__device__ __forceinline__ u64 pack2(float x) {
    u64 r; asm("mov.b64 %0, {%1, %1};" : "=l"(r) : "f"(x)); return r;
}
__device__ __forceinline__ u64 packf2(float2 v) {
    u64 r; asm("mov.b64 %0, {%1, %2};" : "=l"(r) : "f"(v.x), "f"(v.y)); return r;
}
__device__ __forceinline__ void ffma2(u64& d, u64 a, u64 b) {
    asm("fma.rn.f32x2 %0, %1, %2, %0;" : "+l"(d) : "l"(a), "l"(b));
}
__device__ __forceinline__ void addf2(u64& d, u64 a) {
    asm("add.rn.f32x2 %0, %0, %1;" : "+l"(d) : "l"(a));
}
__device__ __forceinline__ float2 unpack2(u64 v) {
    float2 f; asm("mov.b64 {%0, %1}, %2;" : "=f"(f.x), "=f"(f.y) : "l"(v)); return f;
}
__device__ __forceinline__ u64 h2_to_f2(unsigned int h) {
    __half2 hv = *reinterpret_cast<__half2*>(&h);
    return packf2(__half22float2(hv));
}
__device__ __forceinline__ float leaky(float x) { return x >= 0.f ? x : ALPHA * x; }

// ---------------------------------------------------------------------------
// Kernel A: per node, two 64x64 GEMVs over embs:
//   g_H = fp16(leaky(embs @ Q_w + Q_b)),  g_P = embs @ W_w[0:64] + W_b
// block = 256 (8 warps), 4 nodes/warp, grid = 313 (10016, clamped+guarded).
// NPW=4 amortizes the sQ/sP shared reads 4x.
// ---------------------------------------------------------------------------
__global__ __launch_bounds__(256) void qproj_kernel(const float* __restrict__ embs,
                                                    const float* __restrict__ Qw,
                                                    const float* __restrict__ Qb,
                                                    const float* __restrict__ Ww,
                                                    const float* __restrict__ Wb) {
    __shared__ float2 sQ[C_DIM * 32];   // (Qw[c][2l], Qw[c][2l+1])
    __shared__ float2 sP[C_DIM * 32];   // W_top rows 0..63 of Ww
    __shared__ float  sE[8][4][C_DIM];

    const int tid  = threadIdx.x;
    const int lane = tid & 31;
    const int warp = tid >> 5;

    const float2* Q2 = (const float2*)Qw;
    const float2* W2 = (const float2*)Ww;
    for (int i = tid; i < C_DIM * 32; i += 256) { sQ[i] = Q2[i]; sP[i] = W2[i]; }
    __syncthreads();

    int rn[4];
#pragma unroll
    for (int i = 0; i < 4; ++i) {
        rn[i] = blockIdx.x * 32 + warp * 4 + i;
        int node = min(rn[i], N_NODES - 1);
        float2 e = ((const float2*)embs)[node * 32 + lane];
        *(float2*)&sE[warp][i][2 * lane] = e;
    }
    __syncwarp();

    const u64 qb = ((const u64*)Qb)[lane];
    const u64 wb = ((const u64*)Wb)[lane];
    u64 aq[4], ap[4];
#pragma unroll
    for (int i = 0; i < 4; ++i) { aq[i] = qb; ap[i] = wb; }

    const u64* sQ64 = (const u64*)sQ;
    const u64* sP64 = (const u64*)sP;
#pragma unroll
    for (int c = 0; c < C_DIM; c += 4) {
        u64 q0 = sQ64[(c + 0) * 32 + lane], p0 = sP64[(c + 0) * 32 + lane];
        u64 q1 = sQ64[(c + 1) * 32 + lane], p1 = sP64[(c + 1) * 32 + lane];
        u64 q2 = sQ64[(c + 2) * 32 + lane], p2 = sP64[(c + 2) * 32 + lane];
        u64 q3 = sQ64[(c + 3) * 32 + lane], p3 = sP64[(c + 3) * 32 + lane];
#pragma unroll
        for (int i = 0; i < 4; ++i) {
            float4 x = *(const float4*)&sE[warp][i][c];
            u64 x0 = pack2(x.x), x1 = pack2(x.y), x2 = pack2(x.z), x3 = pack2(x.w);
            ffma2(aq[i], x0, q0); ffma2(ap[i], x0, p0);
            ffma2(aq[i], x1, q1); ffma2(ap[i], x1, p1);
            ffma2(aq[i], x2, q2); ffma2(ap[i], x2, p2);
            ffma2(aq[i], x3, q3); ffma2(ap[i], x3, p3);
        }
    }

#pragma unroll
    for (int i = 0; i < 4; ++i) {
        if (rn[i] < N_NODES) {
            float2 h = unpack2(aq[i]);
            h.x = leaky(h.x); h.y = leaky(h.y);
            g_H[rn[i] * 32 + lane] = __float22half2_rn(h);
            ((float2*)g_P)[rn[i] * 32 + lane] = unpack2(ap[i]);
        }
    }
}

// ---------------------------------------------------------------------------
// Kernel B (fused, decoupled latencies, fp16 sV): 1 node/warp, block 256,
// grid 1250 (exact). Random DRAM weight load issues FIRST; all 8 gather
// LDG.128s (address depends only on nbr) issue while it is in flight; the
// fp16 sV fill + g_P prefetch add further cover. GEMM reads sV as half2
// (LDS.32) -> half the crossbar bytes of fp32.
// ---------------------------------------------------------------------------
__global__ __launch_bounds__(256, 4) void agg_kernel(const float* __restrict__ weights,
                                                     const int*   __restrict__ nbr,
                                                     const float* __restrict__ Ww,
                                                     float* __restrict__ out) {
    __shared__ __half2 sVh[H_DIM * 32];  // W_bot rows 64..127 as fp16 (8 KB)
    __shared__ float   sX[8][H_DIM];     // per-warp weighted-sum-hidden vector

    const int tid  = threadIdx.x;
    const int lane = tid & 31;
    const int warp = tid >> 5;

    const int n = blockIdx.x * 8 + warp;   // exact: 1250*8 = 10000

    // ---- 1) neighbor index + 2) random DRAM weight load: issue FIRST ----
    const int   j = nbr[n * K_NBR + lane];
    const float w = __ldcs(&weights[(size_t)n * N_NODES + j]);   // in flight...

    // ---- 3) issue ALL gather loads now (depend only on j, not w) ----
    const int g = lane >> 3;     // group 0..3 -> neighbor k = 4t+g
    const int p = lane & 7;      // 16B chunk -> cols 8p..8p+7 of the 128B row
    const uint4* H4 = (const uint4*)g_H;   // one row = 8 uint4

    uint4 rows[8];
#pragma unroll
    for (int t = 0; t < 8; ++t) {
        int jk = __shfl_sync(0xffffffffu, j, 4 * t + g);
        rows[t] = H4[jk * 8 + p];          // L2 latency overlaps DRAM latency
    }

    // ---- 4) more cover: fill sV as fp16 + prefetch g_P row ----
    // W_bot rows 64..127 = 4096 floats = 1024 float4; thread handles 4.
    const float4* W4 = (const float4*)(Ww + 64 * H_DIM);
#pragma unroll
    for (int i = 0; i < 4; ++i) {
        int f = tid + i * 256;             // float4 index
        float4 v = W4[f];
        int c  = f >> 4;                   // 16 float4 per 64-col row
        int hp = (f & 15) * 2;             // half2 pair index (h/2)
        sVh[c * 32 + hp]     = __floats2half2_rn(v.x, v.y);
        sVh[c * 32 + hp + 1] = __floats2half2_rn(v.z, v.w);
    }

    u64 o = ((const u64*)g_P)[n * 32 + lane];
    __syncthreads();                               // sV ready; w has aged

    // ---- 5) consume random weight: reduce + prescale ----
    float ws = w;
#pragma unroll
    for (int off = 16; off; off >>= 1) ws += __shfl_xor_sync(0xffffffffu, ws, off);
    const float wp_own = w * (1.f / (ws + 1e-6f));

    // ---- 6) weighted accumulate of the in-register rows ----
    u64 acc[4] = {0, 0, 0, 0};
#pragma unroll
    for (int t = 0; t < 8; ++t) {
        float wk = __shfl_sync(0xffffffffu, wp_own, 4 * t + g);
        u64 wp = pack2(wk);
        ffma2(acc[0], wp, h2_to_f2(rows[t].x));
        ffma2(acc[1], wp, h2_to_f2(rows[t].y));
        ffma2(acc[2], wp, h2_to_f2(rows[t].z));
        ffma2(acc[3], wp, h2_to_f2(rows[t].w));
    }

    // butterfly-reduce partial column sums across the 4 groups (lanes ^8, ^16)
#pragma unroll
    for (int d = 0; d < 4; ++d) {
        addf2(acc[d], __shfl_xor_sync(0xffffffffu, acc[d], 8));
        addf2(acc[d], __shfl_xor_sync(0xffffffffu, acc[d], 16));
    }
    if (g == 0) {   // lanes 0..7 hold complete sums for cols 8p..8p+7
#pragma unroll
        for (int d = 0; d < 4; ++d)
            *(float2*)&sX[warp][8 * p + 2 * d] = unpack2(acc[d]);
    }
    __syncwarp();

    // ---- 7) o += wsh @ W_bot (fp16 V, fp32 accumulate) ----
    const unsigned int* sV32 = (const unsigned int*)sVh;
#pragma unroll
    for (int c = 0; c < H_DIM; c += 4) {
        float4 x = *(const float4*)&sX[warp][c];
        ffma2(o, pack2(x.x), h2_to_f2(sV32[(c + 0) * 32 + lane]));
        ffma2(o, pack2(x.y), h2_to_f2(sV32[(c + 1) * 32 + lane]));
        ffma2(o, pack2(x.z), h2_to_f2(sV32[(c + 2) * 32 + lane]));
        ffma2(o, pack2(x.w), h2_to_f2(sV32[(c + 3) * 32 + lane]));
    }

    // ---- 8) leaky + L2-normalize + store ----
    float2 f = unpack2(o);
    f.x = leaky(f.x); f.y = leaky(f.y);
    float ss = f.x * f.x + f.y * f.y;
#pragma unroll
    for (int off = 16; off; off >>= 1) ss += __shfl_xor_sync(0xffffffffu, ss, off);
    const float d = 1.f / (sqrtf(ss) + 1e-6f);
    ((float2*)out)[n * 32 + lane] = make_float2(f.x * d, f.y * d);
}

// ---------------------------------------------------------------------------
// Inputs (metadata order):
//   0 embs (1,10000,64) f32   1 weights (10000,10000) f32
//   2 neighbor_set (10000,32) i32   3 Q_w (64,64) f32   4 Q_b (64,) f32
//   5 W_w (128,64) f32   6 W_b (64,) f32
// ---------------------------------------------------------------------------
extern "C" void kernel_launch(void* const* d_in, const int* in_sizes, int n_in,
                              void* d_out, int out_size) {
    const float* embs    = (const float*)d_in[0];
    const float* weights = (const float*)d_in[1];
    const int*   nbr     = (const int*)  d_in[2];
    const float* Qw      = (const float*)d_in[3];
    const float* Qb      = (const float*)d_in[4];
    const float* Ww      = (const float*)d_in[5];
    const float* Wb      = (const float*)d_in[6];
    float* out = (float*)d_out;

    qproj_kernel<<<313, 256>>>(embs, Qw, Qb, Ww, Wb);
    agg_kernel<<<1250, 256>>>(weights, nbr, Ww, out);
}